// round 1
// baseline (speedup 1.0000x reference)
#include <cuda_runtime.h>
#include <cuda_bf16.h>
#include <math.h>

// ---------------------------------------------------------------------------
// MoE layer: T=8192 tokens, D=1024, MLP=4096, E=8 experts, top-2 routing.
// fp32 baseline: router -> gather per expert -> GEMM1+GELU -> GEMM2+scatter.
// ---------------------------------------------------------------------------

#define T_TOKENS 8192
#define DIM      1024
#define MLP      4096
#define NEXP     8
#define TOPK     2
#define TK_TOT   (T_TOKENS * TOPK)   // 16384 token-expert rows

// ---- scratch (static device globals; no cudaMalloc allowed) ----
__device__ int   g_count[NEXP];
__device__ int   g_offset[NEXP + 1];
__device__ int   g_fill[NEXP];
__device__ int   g_topki[TK_TOT];
__device__ float g_topkg[TK_TOT];
__device__ int   g_tok[TK_TOT];     // gathered token index per local row
__device__ float g_gate[TK_TOT];    // gathered gate per local row
__device__ float g_H[(size_t)TK_TOT * MLP];  // 268 MB intermediate

// ---------------------------------------------------------------------------
// 0) zero output + counts
// ---------------------------------------------------------------------------
__global__ void zero_kernel(float* out, size_t n) {
    size_t i = (size_t)blockIdx.x * blockDim.x + threadIdx.x;
    size_t stride = (size_t)gridDim.x * blockDim.x;
    for (; i < n; i += stride) out[i] = 0.0f;
    if (blockIdx.x == 0 && threadIdx.x < NEXP) g_count[threadIdx.x] = 0;
}

// ---------------------------------------------------------------------------
// 1) router: warp per token. logits = x@Rw + rb + eb; softmax; top2; norm.
// ---------------------------------------------------------------------------
__global__ void router_kernel(const float* __restrict__ x,
                              const float* __restrict__ rw,
                              const float* __restrict__ rb,
                              const float* __restrict__ eb) {
    int warp = (blockIdx.x * blockDim.x + threadIdx.x) >> 5;
    int lane = threadIdx.x & 31;
    if (warp >= T_TOKENS) return;
    const float* xr = x + (size_t)warp * DIM;

    float acc[NEXP];
#pragma unroll
    for (int e = 0; e < NEXP; e++) acc[e] = 0.0f;

    for (int d = lane; d < DIM; d += 32) {
        float xv = xr[d];
        const float* rwd = rw + (size_t)d * NEXP;
#pragma unroll
        for (int e = 0; e < NEXP; e++) acc[e] += xv * rwd[e];
    }
#pragma unroll
    for (int off = 16; off > 0; off >>= 1) {
#pragma unroll
        for (int e = 0; e < NEXP; e++)
            acc[e] += __shfl_xor_sync(0xFFFFFFFFu, acc[e], off);
    }
    if (lane == 0) {
        float p[NEXP];
        float mx = -1e30f;
#pragma unroll
        for (int e = 0; e < NEXP; e++) {
            p[e] = acc[e] + rb[e] + eb[e];
            mx = fmaxf(mx, p[e]);
        }
        float z = 0.0f;
#pragma unroll
        for (int e = 0; e < NEXP; e++) { p[e] = expf(p[e] - mx); z += p[e]; }
        float inv = 1.0f / z;
#pragma unroll
        for (int e = 0; e < NEXP; e++) p[e] *= inv;

        int i1 = 0;
#pragma unroll
        for (int e = 1; e < NEXP; e++) if (p[e] > p[i1]) i1 = e;
        int i2 = (i1 == 0) ? 1 : 0;
#pragma unroll
        for (int e = 0; e < NEXP; e++)
            if (e != i1 && p[e] > p[i2]) i2 = e;

        float s = 1.0f / (p[i1] + p[i2] + 1e-9f);
        g_topki[warp * 2 + 0] = i1;
        g_topkg[warp * 2 + 0] = p[i1] * s;
        g_topki[warp * 2 + 1] = i2;
        g_topkg[warp * 2 + 1] = p[i2] * s;
        atomicAdd(&g_count[i1], 1);
        atomicAdd(&g_count[i2], 1);
    }
}

// ---------------------------------------------------------------------------
// 2) scan: exclusive prefix sum over 8 counts (1 thread)
// ---------------------------------------------------------------------------
__global__ void scan_kernel() {
    int o = 0;
    g_offset[0] = 0;
    for (int e = 0; e < NEXP; e++) {
        g_fill[e] = o;
        o += g_count[e];
        g_offset[e + 1] = o;
    }
}

// ---------------------------------------------------------------------------
// 3) scatter: build gathered (token, gate) lists per expert
// ---------------------------------------------------------------------------
__global__ void scatter_kernel() {
    int idx = blockIdx.x * blockDim.x + threadIdx.x;
    if (idx >= TK_TOT) return;
    int e = g_topki[idx];
    int pos = atomicAdd(&g_fill[e], 1);
    g_tok[pos]  = idx >> 1;
    g_gate[pos] = g_topkg[idx];
}

// ---------------------------------------------------------------------------
// Tiled fp32 GEMM: BM=128, BN=64, BK=16, 256 threads, 8x4 micro-tile.
// ---------------------------------------------------------------------------
#define BM 128
#define BN 64
#define BK 16
#define ASTRIDE (BM + 4)   // padded to dodge bank conflicts on transpose store
#define BSTRIDE (BN + 4)

__device__ __forceinline__ float gelu_exact(float v) {
    return 0.5f * v * (1.0f + erff(v * 0.70710678118654752f));
}

// GEMM1: H[row, n] = gelu( X[tok[row], :] @ W1_e[:, n] + b1_e[n] )
__global__ __launch_bounds__(256)
void gemm1_kernel(const float* __restrict__ x,
                  const float* __restrict__ w1,
                  const float* __restrict__ b1) {
    int e   = blockIdx.z;
    int cnt = g_count[e];
    int m0  = blockIdx.x * BM;
    if (m0 >= cnt) return;
    int off = g_offset[e];
    int n0  = blockIdx.y * BN;

    const float* w1e = w1 + (size_t)e * DIM * MLP;

    __shared__ float As[BK * ASTRIDE];
    __shared__ float Bs[BK * BSTRIDE];
    __shared__ int   stok[BM];

    int tid = threadIdx.x;
    // preload gathered token indices for this M-tile
    if (tid < BM) {
        int mg = m0 + tid;
        stok[tid] = (mg < cnt) ? g_tok[off + mg] : 0;
    }
    __syncthreads();

    int tr = tid >> 4;       // 0..15 -> rows tr*8..tr*8+7
    int tc = tid & 15;       // 0..15 -> cols tc*4..tc*4+3

    float acc[8][4];
#pragma unroll
    for (int i = 0; i < 8; i++)
#pragma unroll
        for (int j = 0; j < 4; j++) acc[i][j] = 0.0f;

    for (int k0 = 0; k0 < DIM; k0 += BK) {
        // load A tile (gathered rows), transpose into As[k][m]
#pragma unroll
        for (int i = 0; i < 2; i++) {
            int idx = tid + i * 256;          // 0..511
            int m   = idx >> 2;               // 0..127
            int c4  = idx & 3;                // 0..3 (float4 within 16 k's)
            float4 v = make_float4(0.f, 0.f, 0.f, 0.f);
            if (m0 + m < cnt)
                v = *(const float4*)&x[(size_t)stok[m] * DIM + k0 + c4 * 4];
            As[(c4 * 4 + 0) * ASTRIDE + m] = v.x;
            As[(c4 * 4 + 1) * ASTRIDE + m] = v.y;
            As[(c4 * 4 + 2) * ASTRIDE + m] = v.z;
            As[(c4 * 4 + 3) * ASTRIDE + m] = v.w;
        }
        // load B tile: W1_e rows [k0, k0+16), cols [n0, n0+64)
        {
            int row = tid >> 4;  // 0..15
            int c4  = tid & 15;  // 0..15
            float4 v = *(const float4*)&w1e[(size_t)(k0 + row) * MLP + n0 + c4 * 4];
            *(float4*)&Bs[row * BSTRIDE + c4 * 4] = v;
        }
        __syncthreads();

#pragma unroll
        for (int kk = 0; kk < BK; kk++) {
            float4 a0 = *(const float4*)&As[kk * ASTRIDE + tr * 8 + 0];
            float4 a1 = *(const float4*)&As[kk * ASTRIDE + tr * 8 + 4];
            float4 b  = *(const float4*)&Bs[kk * BSTRIDE + tc * 4];
            float a[8] = {a0.x, a0.y, a0.z, a0.w, a1.x, a1.y, a1.z, a1.w};
            float bb[4] = {b.x, b.y, b.z, b.w};
#pragma unroll
            for (int i = 0; i < 8; i++)
#pragma unroll
                for (int j = 0; j < 4; j++)
                    acc[i][j] = fmaf(a[i], bb[j], acc[i][j]);
        }
        __syncthreads();
    }

    // epilogue: bias + gelu -> g_H
#pragma unroll
    for (int i = 0; i < 8; i++) {
        int mg = m0 + tr * 8 + i;
        if (mg >= cnt) continue;
        size_t base = (size_t)(off + mg) * MLP + n0 + tc * 4;
#pragma unroll
        for (int j = 0; j < 4; j++) {
            float v = acc[i][j] + b1[(size_t)e * MLP + n0 + tc * 4 + j];
            g_H[base + j] = gelu_exact(v);
        }
    }
}

// GEMM2: out[tok[row], n] += gate[row] * ( H[row, :] @ W2_e[:, n] + b2_e[n] )
__global__ __launch_bounds__(256)
void gemm2_kernel(const float* __restrict__ w2,
                  const float* __restrict__ b2,
                  float* __restrict__ out) {
    int e   = blockIdx.z;
    int cnt = g_count[e];
    int m0  = blockIdx.x * BM;
    if (m0 >= cnt) return;
    int off = g_offset[e];
    int n0  = blockIdx.y * BN;

    const float* w2e = w2 + (size_t)e * MLP * DIM;

    __shared__ float As[BK * ASTRIDE];
    __shared__ float Bs[BK * BSTRIDE];

    int tid = threadIdx.x;
    int tr = tid >> 4;
    int tc = tid & 15;

    float acc[8][4];
#pragma unroll
    for (int i = 0; i < 8; i++)
#pragma unroll
        for (int j = 0; j < 4; j++) acc[i][j] = 0.0f;

    for (int k0 = 0; k0 < MLP; k0 += BK) {
#pragma unroll
        for (int i = 0; i < 2; i++) {
            int idx = tid + i * 256;
            int m   = idx >> 2;
            int c4  = idx & 3;
            float4 v = make_float4(0.f, 0.f, 0.f, 0.f);
            if (m0 + m < cnt)
                v = *(const float4*)&g_H[(size_t)(off + m0 + m) * MLP + k0 + c4 * 4];
            As[(c4 * 4 + 0) * ASTRIDE + m] = v.x;
            As[(c4 * 4 + 1) * ASTRIDE + m] = v.y;
            As[(c4 * 4 + 2) * ASTRIDE + m] = v.z;
            As[(c4 * 4 + 3) * ASTRIDE + m] = v.w;
        }
        {
            int row = tid >> 4;
            int c4  = tid & 15;
            float4 v = *(const float4*)&w2e[(size_t)(k0 + row) * DIM + n0 + c4 * 4];
            *(float4*)&Bs[row * BSTRIDE + c4 * 4] = v;
        }
        __syncthreads();

#pragma unroll
        for (int kk = 0; kk < BK; kk++) {
            float4 a0 = *(const float4*)&As[kk * ASTRIDE + tr * 8 + 0];
            float4 a1 = *(const float4*)&As[kk * ASTRIDE + tr * 8 + 4];
            float4 b  = *(const float4*)&Bs[kk * BSTRIDE + tc * 4];
            float a[8] = {a0.x, a0.y, a0.z, a0.w, a1.x, a1.y, a1.z, a1.w};
            float bb[4] = {b.x, b.y, b.z, b.w};
#pragma unroll
            for (int i = 0; i < 8; i++)
#pragma unroll
                for (int j = 0; j < 4; j++)
                    acc[i][j] = fmaf(a[i], bb[j], acc[i][j]);
        }
        __syncthreads();
    }

    // epilogue: bias, gate-scale, scatter-add into output
#pragma unroll
    for (int i = 0; i < 8; i++) {
        int mg = m0 + tr * 8 + i;
        if (mg >= cnt) continue;
        int   tok = g_tok[off + mg];
        float g   = g_gate[off + mg];
        float* orow = out + (size_t)tok * DIM + n0 + tc * 4;
#pragma unroll
        for (int j = 0; j < 4; j++) {
            float v = acc[i][j] + b2[(size_t)e * DIM + n0 + tc * 4 + j];
            atomicAdd(&orow[j], g * v);
        }
    }
}

// ---------------------------------------------------------------------------
// launch
// ---------------------------------------------------------------------------
extern "C" void kernel_launch(void* const* d_in, const int* in_sizes, int n_in,
                              void* d_out, int out_size) {
    const float* hidden  = (const float*)d_in[0];  // [4,2048,1024]
    const float* rw      = (const float*)d_in[1];  // [1024,8]
    const float* rb      = (const float*)d_in[2];  // [8]
    const float* eb      = (const float*)d_in[3];  // [8]
    const float* w1      = (const float*)d_in[4];  // [8,1024,4096]
    const float* b1      = (const float*)d_in[5];  // [8,4096]
    const float* w2      = (const float*)d_in[6];  // [8,4096,1024]
    const float* b2      = (const float*)d_in[7];  // [8,1024]
    float* out = (float*)d_out;

    // 0) zero output + counts
    zero_kernel<<<2048, 256>>>(out, (size_t)out_size);

    // 1) router: warp per token
    router_kernel<<<(T_TOKENS * 32) / 128, 128>>>(hidden, rw, rb, eb);

    // 2) offsets
    scan_kernel<<<1, 1>>>();

    // 3) scatter into per-expert lists
    scatter_kernel<<<TK_TOT / 256, 256>>>();

    // 4) GEMM1 + GELU   grid: (Mtiles=64, Ntiles=4096/64=64, E=8)
    {
        dim3 grid(T_TOKENS / BM, MLP / BN, NEXP);
        gemm1_kernel<<<grid, 256>>>(hidden, w1, b1);
    }
    // 5) GEMM2 + gated scatter-add   grid: (64, 1024/64=16, 8)
    {
        dim3 grid(T_TOKENS / BM, DIM / BN, NEXP);
        gemm2_kernel<<<grid, 256>>>(w2, b2, out);
    }
}

// round 4
// speedup vs baseline: 5.0481x; 5.0481x over previous
#include <cuda_runtime.h>
#include <cuda_fp16.h>
#include <math.h>
#include <stdint.h>

// ---------------------------------------------------------------------------
// MoE: T=8192 tokens, D=1024, MLP=4096, E=8, top-2.
// fp16 HMMA (mma.sync) path: router -> gather -> GEMM1(+GELU) -> GEMM2 -> combine
// NOTE: device-global scratch addresses MUST be resolved via
// cudaGetSymbolAddress on the host (GB300 ATS makes the host-shadow-pointer
// bug a silent zero-read instead of a crash).
// ---------------------------------------------------------------------------

#define T_TOKENS 8192
#define DIM      1024
#define MLP      4096
#define NEXP     8
#define TK_TOT   (T_TOKENS * 2)

// ---- scratch (device globals; no cudaMalloc allowed) ----
__device__ int   g_count[NEXP];
__device__ int   g_offset[NEXP + 1];
__device__ int   g_fill[NEXP];
__device__ int   g_topki[TK_TOT];
__device__ float g_topkg[TK_TOT];
__device__ int   g_tok[TK_TOT];
__device__ int   g_pos[TK_TOT];
__device__ __align__(16) __half g_xh [(size_t)T_TOKENS * DIM];
__device__ __align__(16) __half g_w1t[(size_t)NEXP * MLP * DIM];  // [e][n=4096][k=1024]
__device__ __align__(16) __half g_w2t[(size_t)NEXP * DIM * MLP];  // [e][n=1024][k=4096]
__device__ __align__(16) __half g_Hh [(size_t)TK_TOT * MLP];
__device__ __align__(16) float  g_Y  [(size_t)TK_TOT * DIM];

// ---------------------------------------------------------------------------
// PTX helpers (sm_80-era instructions only; legal on plain sm_103 target)
// ---------------------------------------------------------------------------
__device__ __forceinline__ uint32_t smem_u32(const void* p) {
    uint32_t a;
    asm("{ .reg .u64 t; cvta.to.shared.u64 t, %1; cvt.u32.u64 %0, t; }" : "=r"(a) : "l"(p));
    return a;
}
__device__ __forceinline__ void cp16(uint32_t dst, const void* src) {
    asm volatile("cp.async.cg.shared.global [%0], [%1], 16;" :: "r"(dst), "l"(src) : "memory");
}
__device__ __forceinline__ void cp_commit() { asm volatile("cp.async.commit_group;" ::: "memory"); }

__device__ __forceinline__ void ldsm_x4(uint32_t* r, uint32_t addr) {
    asm volatile("ldmatrix.sync.aligned.m8n8.x4.shared.b16 {%0,%1,%2,%3}, [%4];"
                 : "=r"(r[0]), "=r"(r[1]), "=r"(r[2]), "=r"(r[3]) : "r"(addr));
}
__device__ __forceinline__ void ldsm_x2(uint32_t* r, uint32_t addr) {
    asm volatile("ldmatrix.sync.aligned.m8n8.x2.shared.b16 {%0,%1}, [%2];"
                 : "=r"(r[0]), "=r"(r[1]) : "r"(addr));
}
__device__ __forceinline__ void mma16816(float* c, const uint32_t* a, const uint32_t* b) {
    asm volatile("mma.sync.aligned.m16n8k16.row.col.f32.f16.f16.f32 "
                 "{%0,%1,%2,%3}, {%4,%5,%6,%7}, {%8,%9}, {%0,%1,%2,%3};"
                 : "+f"(c[0]), "+f"(c[1]), "+f"(c[2]), "+f"(c[3])
                 : "r"(a[0]), "r"(a[1]), "r"(a[2]), "r"(a[3]), "r"(b[0]), "r"(b[1]));
}

__device__ __forceinline__ float gelu_exact(float v) {
    return 0.5f * v * (1.0f + erff(v * 0.70710678118654752f));
}

// ---------------------------------------------------------------------------
// small kernels
// ---------------------------------------------------------------------------
__global__ void init_kernel() {
    if (threadIdx.x < NEXP) g_count[threadIdx.x] = 0;
}

__global__ void router_kernel(const float* __restrict__ x,
                              const float* __restrict__ rw,
                              const float* __restrict__ rb,
                              const float* __restrict__ eb) {
    int warp = (blockIdx.x * blockDim.x + threadIdx.x) >> 5;
    int lane = threadIdx.x & 31;
    if (warp >= T_TOKENS) return;
    const float* xr = x + (size_t)warp * DIM;
    float acc[NEXP];
#pragma unroll
    for (int e = 0; e < NEXP; e++) acc[e] = 0.0f;
    for (int d = lane; d < DIM; d += 32) {
        float xv = xr[d];
        const float* rwd = rw + (size_t)d * NEXP;
#pragma unroll
        for (int e = 0; e < NEXP; e++) acc[e] += xv * rwd[e];
    }
#pragma unroll
    for (int off = 16; off > 0; off >>= 1)
#pragma unroll
        for (int e = 0; e < NEXP; e++)
            acc[e] += __shfl_xor_sync(0xFFFFFFFFu, acc[e], off);
    if (lane == 0) {
        float p[NEXP];
        float mx = -1e30f;
#pragma unroll
        for (int e = 0; e < NEXP; e++) { p[e] = acc[e] + rb[e] + eb[e]; mx = fmaxf(mx, p[e]); }
        float z = 0.0f;
#pragma unroll
        for (int e = 0; e < NEXP; e++) { p[e] = expf(p[e] - mx); z += p[e]; }
        float inv = 1.0f / z;
#pragma unroll
        for (int e = 0; e < NEXP; e++) p[e] *= inv;
        int i1 = 0;
#pragma unroll
        for (int e = 1; e < NEXP; e++) if (p[e] > p[i1]) i1 = e;
        int i2 = (i1 == 0) ? 1 : 0;
#pragma unroll
        for (int e = 0; e < NEXP; e++) if (e != i1 && p[e] > p[i2]) i2 = e;
        float s = 1.0f / (p[i1] + p[i2] + 1e-9f);
        g_topki[warp * 2 + 0] = i1;  g_topkg[warp * 2 + 0] = p[i1] * s;
        g_topki[warp * 2 + 1] = i2;  g_topkg[warp * 2 + 1] = p[i2] * s;
        atomicAdd(&g_count[i1], 1);
        atomicAdd(&g_count[i2], 1);
    }
}

__global__ void scan_kernel() {
    int o = 0;
    g_offset[0] = 0;
    for (int e = 0; e < NEXP; e++) {
        g_fill[e] = o;
        o += g_count[e];
        g_offset[e + 1] = o;
    }
}

__global__ void scatter_kernel() {
    int idx = blockIdx.x * blockDim.x + threadIdx.x;
    if (idx >= TK_TOT) return;
    int e = g_topki[idx];
    int pos = atomicAdd(&g_fill[e], 1);
    g_tok[pos] = idx >> 1;
    g_pos[idx] = pos;
}

__global__ void convert_x_kernel(const float* __restrict__ x) {
    size_t i = ((size_t)blockIdx.x * blockDim.x + threadIdx.x) * 8;
    if (i >= (size_t)T_TOKENS * DIM) return;
    float4 a = *(const float4*)&x[i];
    float4 b = *(const float4*)&x[i + 4];
    __half h[8];
    h[0] = __float2half_rn(a.x); h[1] = __float2half_rn(a.y);
    h[2] = __float2half_rn(a.z); h[3] = __float2half_rn(a.w);
    h[4] = __float2half_rn(b.x); h[5] = __float2half_rn(b.y);
    h[6] = __float2half_rn(b.z); h[7] = __float2half_rn(b.w);
    *(uint4*)&g_xh[i] = *(uint4*)h;
}

// src: [E][K][N] fp32 -> dst: [E][N][K] fp16
__global__ void transpose_w_kernel(const float* __restrict__ src, __half* __restrict__ dst,
                                   int K, int N) {
    __shared__ float tile[32][33];
    size_t base = (size_t)blockIdx.z * K * N;
    int n0 = blockIdx.x * 32, k0 = blockIdx.y * 32;
    int tx = threadIdx.x, ty = threadIdx.y;
#pragma unroll
    for (int i = 0; i < 32; i += 8)
        tile[ty + i][tx] = src[base + (size_t)(k0 + ty + i) * N + n0 + tx];
    __syncthreads();
#pragma unroll
    for (int i = 0; i < 32; i += 8)
        dst[base + (size_t)(n0 + ty + i) * K + k0 + tx] = __float2half_rn(tile[tx][ty + i]);
}

__global__ void combine_kernel(const float* __restrict__ Y, float* __restrict__ out) {
    int gid = blockIdx.x * blockDim.x + threadIdx.x;
    int t = gid >> 8;
    int c = (gid & 255) * 4;
    int p0 = g_pos[2 * t], p1 = g_pos[2 * t + 1];
    float g0 = g_topkg[2 * t], g1 = g_topkg[2 * t + 1];
    float4 y0 = *(const float4*)&Y[(size_t)p0 * DIM + c];
    float4 y1 = *(const float4*)&Y[(size_t)p1 * DIM + c];
    float4 o;
    o.x = g0 * y0.x + g1 * y1.x;
    o.y = g0 * y0.y + g1 * y1.y;
    o.z = g0 * y0.z + g1 * y1.z;
    o.w = g0 * y0.w + g1 * y1.w;
    *(float4*)&out[(size_t)t * DIM + c] = o;
}

// ---------------------------------------------------------------------------
// HMMA GEMM: BM=128 x BN=128, BK=32, 256 threads (8 warps, 2x4, 64x32 tiles),
// 3-stage cp.async pipeline, padded smem (stride 80B) for conflict-free ldmatrix.
// ---------------------------------------------------------------------------
#define BM 128
#define BN 128
#define BK 32
#define STAGES 3
#define SKA 40                        // halves per smem row (32 + 8 pad)
#define STAGE_BYTES (BM * SKA * 2)    // 10240 per operand per stage
#define SMEM_TOTAL (2 * STAGES * STAGE_BYTES + BM * 4 + BN * 4)

template<int KTOT, bool IS_G1>
__global__ __launch_bounds__(256)
void gemm_kernel(const __half* __restrict__ Asrc,
                 const __half* __restrict__ Bsrc,
                 const float* __restrict__ bias,
                 __half* __restrict__ Hout,
                 float* __restrict__ Yout) {
    constexpr int NB = IS_G1 ? MLP : DIM;
    constexpr int TT = KTOT / BK;

    const int e   = blockIdx.z;
    const int cnt = g_count[e];
    const int m0  = blockIdx.x * BM;
    if (m0 >= cnt) return;
    const int off = g_offset[e];
    const int n0  = blockIdx.y * BN;

    extern __shared__ char smem[];
    const uint32_t sb   = smem_u32(smem);
    const uint32_t a_sm = sb;
    const uint32_t b_sm = sb + STAGES * STAGE_BYTES;
    int*   rows_s = (int*)(smem + 2 * STAGES * STAGE_BYTES);
    float* bias_s = (float*)(rows_s + BM);

    const int tid  = threadIdx.x;
    const int lane = tid & 31;
    const int wid  = tid >> 5;
    const int wm   = (wid & 1) * 64;   // warp M offset
    const int wn   = (wid >> 1) * 32;  // warp N offset

    if (tid < BM) {
        int mg = m0 + tid;
        int r  = (mg < cnt) ? mg : (cnt - 1);
        rows_s[tid] = IS_G1 ? g_tok[off + r] : (off + r);
    } else {
        int j = tid - BM;
        bias_s[j] = bias[(size_t)e * NB + n0 + j];
    }
    __syncthreads();

    // ---- load geometry: 512 16B chunks per operand per stage; 2 per thread ----
    const int id0 = tid, id1 = tid + 256;
    const int r0 = id0 >> 2, c0 = id0 & 3;
    const int r1 = id1 >> 2, c1 = id1 & 3;
    const __half* aG0 = Asrc + (size_t)rows_s[r0] * KTOT + c0 * 8;
    const __half* aG1 = Asrc + (size_t)rows_s[r1] * KTOT + c1 * 8;
    const __half* bG0 = Bsrc + ((size_t)e * NB + n0 + r0) * KTOT + c0 * 8;
    const __half* bG1 = Bsrc + ((size_t)e * NB + n0 + r1) * KTOT + c1 * 8;
    const uint32_t aS0 = a_sm + r0 * 80 + c0 * 16;
    const uint32_t aS1 = a_sm + r1 * 80 + c1 * 16;
    const uint32_t bS0 = b_sm + r0 * 80 + c0 * 16;
    const uint32_t bS1 = b_sm + r1 * 80 + c1 * 16;

    auto load_stage = [&](int t, int buf) {
        const int k0 = t * BK;
        const uint32_t so = buf * STAGE_BYTES;
        cp16(aS0 + so, aG0 + k0);
        cp16(aS1 + so, aG1 + k0);
        cp16(bS0 + so, bG0 + k0);
        cp16(bS1 + so, bG1 + k0);
        cp_commit();
    };

    float acc[4][4][4];
#pragma unroll
    for (int i = 0; i < 4; i++)
#pragma unroll
        for (int j = 0; j < 4; j++)
#pragma unroll
            for (int q = 0; q < 4; q++) acc[i][j][q] = 0.0f;

    load_stage(0, 0);
    load_stage(1, 1);

    // precomputed ldmatrix lane addresses (stage-base relative)
    const uint32_t a_ld = a_sm + (wm + (lane & 15)) * 80 + (lane >> 4) * 16;
    const uint32_t b_ld = b_sm + (wn + (lane & 7)) * 80 + ((lane >> 3) & 1) * 16;

    for (int t = 0; t < TT; t++) {
        const int buf = t % STAGES;
        if (t < TT - 1) asm volatile("cp.async.wait_group 1;" ::: "memory");
        else            asm volatile("cp.async.wait_group 0;" ::: "memory");
        __syncthreads();
        if (t + 2 < TT) load_stage(t + 2, (t + 2) % STAGES);

        const uint32_t so = buf * STAGE_BYTES;
#pragma unroll
        for (int kk = 0; kk < 2; kk++) {
            uint32_t a[4][4], b[4][2];
#pragma unroll
            for (int i = 0; i < 4; i++)
                ldsm_x4(a[i], a_ld + so + i * 16 * 80 + kk * 32);
#pragma unroll
            for (int j = 0; j < 4; j++)
                ldsm_x2(b[j], b_ld + so + j * 8 * 80 + kk * 32);
#pragma unroll
            for (int i = 0; i < 4; i++)
#pragma unroll
                for (int j = 0; j < 4; j++)
                    mma16816(acc[i][j], a[i], b[j]);
        }
        __syncthreads();
    }

    // ---- epilogue ----
    const int grow = lane >> 2;
    const int gcol = (lane & 3) * 2;
#pragma unroll
    for (int i = 0; i < 4; i++) {
        const int mlo = m0 + wm + i * 16 + grow;
        const int mhi = mlo + 8;
#pragma unroll
        for (int j = 0; j < 4; j++) {
            const int cb  = wn + j * 8 + gcol;      // col within tile
            const int col = n0 + cb;
            const float b0 = bias_s[cb], b1 = bias_s[cb + 1];
            if (IS_G1) {
                if (mlo < cnt) {
                    __half2 h = __floats2half2_rn(gelu_exact(acc[i][j][0] + b0),
                                                  gelu_exact(acc[i][j][1] + b1));
                    *(__half2*)&Hout[(size_t)(off + mlo) * MLP + col] = h;
                }
                if (mhi < cnt) {
                    __half2 h = __floats2half2_rn(gelu_exact(acc[i][j][2] + b0),
                                                  gelu_exact(acc[i][j][3] + b1));
                    *(__half2*)&Hout[(size_t)(off + mhi) * MLP + col] = h;
                }
            } else {
                if (mlo < cnt) {
                    float2 v = make_float2(acc[i][j][0] + b0, acc[i][j][1] + b1);
                    *(float2*)&Yout[(size_t)(off + mlo) * DIM + col] = v;
                }
                if (mhi < cnt) {
                    float2 v = make_float2(acc[i][j][2] + b0, acc[i][j][3] + b1);
                    *(float2*)&Yout[(size_t)(off + mhi) * DIM + col] = v;
                }
            }
        }
    }
}

// ---------------------------------------------------------------------------
// launch
// ---------------------------------------------------------------------------
extern "C" void kernel_launch(void* const* d_in, const int* in_sizes, int n_in,
                              void* d_out, int out_size) {
    const float* hidden = (const float*)d_in[0];
    const float* rw     = (const float*)d_in[1];
    const float* rb     = (const float*)d_in[2];
    const float* eb     = (const float*)d_in[3];
    const float* w1     = (const float*)d_in[4];
    const float* b1     = (const float*)d_in[5];
    const float* w2     = (const float*)d_in[6];
    const float* b2     = (const float*)d_in[7];
    float* out = (float*)d_out;

    // Resolve REAL device addresses of scratch globals (host shadow addresses
    // are silently dereferenceable via ATS on GB300 and read zeros).
    void *p_xh, *p_w1t, *p_w2t, *p_Hh, *p_Y;
    cudaGetSymbolAddress(&p_xh,  g_xh);
    cudaGetSymbolAddress(&p_w1t, g_w1t);
    cudaGetSymbolAddress(&p_w2t, g_w2t);
    cudaGetSymbolAddress(&p_Hh,  g_Hh);
    cudaGetSymbolAddress(&p_Y,   g_Y);
    __half* xh  = (__half*)p_xh;
    __half* w1t = (__half*)p_w1t;
    __half* w2t = (__half*)p_w2t;
    __half* Hh  = (__half*)p_Hh;
    float*  Y   = (float*)p_Y;

    cudaFuncSetAttribute(gemm_kernel<DIM, true>,
                         cudaFuncAttributeMaxDynamicSharedMemorySize, SMEM_TOTAL);
    cudaFuncSetAttribute(gemm_kernel<MLP, false>,
                         cudaFuncAttributeMaxDynamicSharedMemorySize, SMEM_TOTAL);

    init_kernel<<<1, 32>>>();
    router_kernel<<<(T_TOKENS * 32) / 128, 128>>>(hidden, rw, rb, eb);
    scan_kernel<<<1, 1>>>();
    scatter_kernel<<<TK_TOT / 256, 256>>>();

    convert_x_kernel<<<(T_TOKENS * DIM / 8) / 256, 256>>>(hidden);
    {
        dim3 blk(32, 8);
        dim3 g1(MLP / 32, DIM / 32, NEXP);   // w1: K=1024, N=4096
        transpose_w_kernel<<<g1, blk>>>(w1, w1t, DIM, MLP);
        dim3 g2(DIM / 32, MLP / 32, NEXP);   // w2: K=4096, N=1024
        transpose_w_kernel<<<g2, blk>>>(w2, w2t, MLP, DIM);
    }

    {
        dim3 grid(T_TOKENS / BM, MLP / BN, NEXP);   // (64, 32, 8)
        gemm_kernel<DIM, true><<<grid, 256, SMEM_TOTAL>>>(xh, w1t, b1, Hh, Y);
    }
    {
        dim3 grid(T_TOKENS / BM, DIM / BN, NEXP);   // (64, 8, 8)
        gemm_kernel<MLP, false><<<grid, 256, SMEM_TOTAL>>>(Hh, w2t, b2, Hh, Y);
    }
    combine_kernel<<<(T_TOKENS * DIM / 4) / 256, 256>>>(Y, out);
}